// round 1
// baseline (speedup 1.0000x reference)
#include <cuda_runtime.h>
#include <cstdint>

// ---------------------------------------------------------------------------
// B-spline basis (cubic, DF=16) via de Boor's algorithm.
// KNOTS = [0,0,0] ++ linspace(0, 1+1e-7, 14) ++ [1,1,1]   (fp32, numpy-exact)
// numpy linspace: step computed in f64, values i*step (f64) cast to f32,
// endpoint set exactly to stop.
// ---------------------------------------------------------------------------

#define STEP_D (1.0000001 / 13.0)
#define KP(i)  ((float)((double)(i) * STEP_D))

__constant__ float KN[20] = {
    0.0f, 0.0f, 0.0f,
    0.0f,                                   // KN[3]  = linspace[0]
    KP(1),  KP(2),  KP(3),  KP(4),  KP(5),  KP(6),
    KP(7),  KP(8),  KP(9),  KP(10), KP(11), KP(12),
    (float)1.0000001,                       // KN[16] = linspace endpoint (exact stop)
    1.0f, 1.0f, 1.0f
};

#define INV_H ((float)(13.0 / 1.0000001))

#define TPB 256

__global__ __launch_bounds__(TPB) void bspline_kernel(
    const float* __restrict__ ts,
    float4* __restrict__ out4,
    int n)
{
    __shared__ float4 sN[TPB];
    __shared__ int    sJ[TPB];

    const int tid  = threadIdx.x;
    const int base = blockIdx.x * TPB;
    const int gi   = base + tid;

    // ---- Phase 1: one element per thread, de Boor for the 4 nonzero basis ----
    const int li = (gi < n) ? gi : (n - 1);
    const float t = ts[li];

    // Find knot span j such that KN[3+j] <= t < KN[4+j], j in [0,12].
    int j = (int)(t * INV_H);
    j = max(0, min(12, j));
    // Boundary correction so the span matches the reference's indicator exactly.
    while (j > 0  && t <  KN[3 + j]) --j;
    while (j < 12 && t >= KN[4 + j]) ++j;

    const int span = j + 3;
    const float l1 = t - KN[span];
    const float l2 = t - KN[span - 1];
    const float l3 = t - KN[span - 2];
    const float r1 = KN[span + 1] - t;
    const float r2 = KN[span + 2] - t;
    const float r3 = KN[span + 3] - t;

    float N0 = 1.0f, N1, N2, N3, sv, tp;
    // r = 1
    tp = __fdividef(N0, r1 + l1); N0 = r1 * tp; N1 = l1 * tp;
    // r = 2
    tp = __fdividef(N0, r1 + l2); N0 = r1 * tp; sv = l2 * tp;
    tp = __fdividef(N1, r2 + l1); N1 = sv + r2 * tp; N2 = l1 * tp;
    // r = 3
    tp = __fdividef(N0, r1 + l3); N0 = r1 * tp; sv = l3 * tp;
    tp = __fdividef(N1, r2 + l2); N1 = sv + r2 * tp; sv = l2 * tp;
    tp = __fdividef(N2, r3 + l1); N2 = sv + r3 * tp; N3 = l1 * tp;

    sN[tid] = make_float4(N0, N1, N2, N3);
    sJ[tid] = j;
    __syncthreads();

    // ---- Phase 2: fully coalesced store of the block's 256x16 fp32 tile ----
    // Output float4 slot f (0..1023) within block = element (f>>2), chunk (f&3).
    float4* oblock = out4 + (size_t)base * 4;
    const long long limit4 = (long long)n * 4;

    #pragma unroll
    for (int i = 0; i < 4; i++) {
        const int f = tid + TPB * i;
        const int e = f >> 2;
        const int c = f & 3;
        const float4 nv = sN[e];
        const int jj = sJ[e];
        const int cb = c * 4 - jj;   // column of .x relative to first nonzero basis

        float4 o;
        o.x = (cb ==  0) ? nv.x : (cb ==  1) ? nv.y : (cb ==  2) ? nv.z : (cb ==  3) ? nv.w : 0.0f;
        o.y = (cb == -1) ? nv.x : (cb ==  0) ? nv.y : (cb ==  1) ? nv.z : (cb ==  2) ? nv.w : 0.0f;
        o.z = (cb == -2) ? nv.x : (cb == -1) ? nv.y : (cb ==  0) ? nv.z : (cb ==  1) ? nv.w : 0.0f;
        o.w = (cb == -3) ? nv.x : (cb == -2) ? nv.y : (cb == -1) ? nv.z : (cb ==  0) ? nv.w : 0.0f;

        if ((long long)base * 4 + f < limit4)
            oblock[f] = o;
    }
}

extern "C" void kernel_launch(void* const* d_in, const int* in_sizes, int n_in,
                              void* d_out, int out_size)
{
    const float* ts = (const float*)d_in[0];
    float4* out4 = (float4*)d_out;
    const int n = in_sizes[0];           // 32 * 131072 = 4194304 elements
    const int blocks = (n + TPB - 1) / TPB;
    bspline_kernel<<<blocks, TPB>>>(ts, out4, n);
}

// round 3
// speedup vs baseline: 1.8431x; 1.8431x over previous
#include <cuda_runtime.h>
#include <cstdint>

// ---------------------------------------------------------------------------
// B-spline basis (cubic, DF=16) via de Boor's algorithm.
// KNOTS = [0,0,0] ++ linspace(0, 1+1e-7, 14) ++ [1,1,1]   (fp32, numpy-exact)
// vs R1: (a) knots staged in SHARED memory — register-indexed __constant__
// loads serialize per unique address on the half-rate constant port;
// (b) span correction is two predicated single steps instead of while-loops
// (kills the BSSY/BSYNC divergence envelope).
// ---------------------------------------------------------------------------

#define STEP_D (1.0000001 / 13.0)
#define KP(i)  ((float)((double)(i) * STEP_D))

__constant__ float KN[20] = {
    0.0f, 0.0f, 0.0f,
    0.0f,                                   // KN[3]  = linspace[0]
    KP(1),  KP(2),  KP(3),  KP(4),  KP(5),  KP(6),
    KP(7),  KP(8),  KP(9),  KP(10), KP(11), KP(12),
    (float)1.0000001,                       // KN[16] = linspace endpoint (exact stop)
    1.0f, 1.0f, 1.0f
};

#define INV_H ((float)(13.0 / 1.0000001))

#define TPB 256

__global__ __launch_bounds__(TPB) void bspline_kernel(
    const float* __restrict__ ts,
    float4* __restrict__ out4,
    int n)
{
    __shared__ float  sKN[20];
    __shared__ float4 sN[TPB];
    __shared__ int    sJ[TPB];

    const int tid  = threadIdx.x;
    const int base = blockIdx.x * TPB;
    const int gi   = base + tid;

    if (tid < 20) sKN[tid] = KN[tid];

    // Issue the global load before the barrier so its latency overlaps.
    const int li = (gi < n) ? gi : (n - 1);
    const float t = ts[li];

    __syncthreads();

    // ---- Phase 1: one element per thread, de Boor for the 4 nonzero basis ----
    // Find knot span j such that sKN[3+j] <= t < sKN[4+j], j in [0,12].
    // Interior knots are i*STEP rounded to fp32, so the float estimate
    // j = floor(t*INV_H) is off by at most one step in either direction.
    int j = (int)(t * INV_H);
    j = max(0, min(12, j));
    // Predicated single-step corrections (no divergent loops).
    j -= (j > 0)  && (t <  sKN[3 + j]);
    j += (j < 12) && (t >= sKN[4 + j]);

    const int span = j + 3;
    const float l1 = t - sKN[span];
    const float l2 = t - sKN[span - 1];
    const float l3 = t - sKN[span - 2];
    const float r1 = sKN[span + 1] - t;
    const float r2 = sKN[span + 2] - t;
    const float r3 = sKN[span + 3] - t;

    float N0 = 1.0f, N1, N2, N3, sv, tp;
    // r = 1
    tp = __fdividef(N0, r1 + l1); N0 = r1 * tp; N1 = l1 * tp;
    // r = 2
    tp = __fdividef(N0, r1 + l2); N0 = r1 * tp; sv = l2 * tp;
    tp = __fdividef(N1, r2 + l1); N1 = sv + r2 * tp; N2 = l1 * tp;
    // r = 3
    tp = __fdividef(N0, r1 + l3); N0 = r1 * tp; sv = l3 * tp;
    tp = __fdividef(N1, r2 + l2); N1 = sv + r2 * tp; sv = l2 * tp;
    tp = __fdividef(N2, r3 + l1); N2 = sv + r3 * tp; N3 = l1 * tp;

    sN[tid] = make_float4(N0, N1, N2, N3);
    sJ[tid] = j;
    __syncthreads();

    // ---- Phase 2: fully coalesced store of the block's 256x16 fp32 tile ----
    // Output float4 slot f (0..1023) within block = element (f>>2), chunk (f&3).
    float4* oblock = out4 + (size_t)base * 4;
    const long long limit4 = (long long)n * 4;

    #pragma unroll
    for (int i = 0; i < 4; i++) {
        const int f = tid + TPB * i;
        const int e = f >> 2;
        const int c = f & 3;
        const float4 nv = sN[e];
        const int jj = sJ[e];
        const int cb = c * 4 - jj;   // column of .x relative to first nonzero basis

        float4 o;
        o.x = (cb ==  0) ? nv.x : (cb ==  1) ? nv.y : (cb ==  2) ? nv.z : (cb ==  3) ? nv.w : 0.0f;
        o.y = (cb == -1) ? nv.x : (cb ==  0) ? nv.y : (cb ==  1) ? nv.z : (cb ==  2) ? nv.w : 0.0f;
        o.z = (cb == -2) ? nv.x : (cb == -1) ? nv.y : (cb ==  0) ? nv.z : (cb ==  1) ? nv.w : 0.0f;
        o.w = (cb == -3) ? nv.x : (cb == -2) ? nv.y : (cb == -1) ? nv.z : (cb ==  0) ? nv.w : 0.0f;

        if ((long long)base * 4 + f < limit4)
            oblock[f] = o;
    }
}

extern "C" void kernel_launch(void* const* d_in, const int* in_sizes, int n_in,
                              void* d_out, int out_size)
{
    const float* ts = (const float*)d_in[0];
    float4* out4 = (float4*)d_out;
    const int n = in_sizes[0];           // 32 * 131072 = 4194304 elements
    const int blocks = (n + TPB - 1) / TPB;
    bspline_kernel<<<blocks, TPB>>>(ts, out4, n);
}

// round 5
// speedup vs baseline: 3.1776x; 1.7240x over previous
#include <cuda_runtime.h>
#include <cstdint>

// ---------------------------------------------------------------------------
// B-spline basis (cubic, DF=16) via de Boor's algorithm.
// KNOTS = [0,0,0] ++ linspace(0, 1+1e-7, 14) ++ [1,1,1]   (fp32, numpy-exact)
// vs R3: replaced the register select-expansion (≈120 ALU instrs/thread) with
// a zeroed padded smem tile + 4-float scatter at column j, then a raw
// LDS.128/STG.128 copy-out. Owner re-zeros its 4 cells after copy-out, so the
// full tile zero-fill runs once per block. Blocks are persistent over 8 tiles.
// ---------------------------------------------------------------------------

#define STEP_D (1.0000001 / 13.0)
#define KP(i)  ((float)((double)(i) * STEP_D))

__constant__ float KN[20] = {
    0.0f, 0.0f, 0.0f,
    0.0f,                                   // KN[3]  = linspace[0]
    KP(1),  KP(2),  KP(3),  KP(4),  KP(5),  KP(6),
    KP(7),  KP(8),  KP(9),  KP(10), KP(11), KP(12),
    (float)1.0000001,                       // KN[16] = linspace endpoint (exact stop)
    1.0f, 1.0f, 1.0f
};

#define INV_H ((float)(13.0 / 1.0000001))

#define TPB   256
#define TILES 8                 // elements per block = TPB * TILES
#define RSTR  20                // padded row stride in floats (16 data + 4 pad)

__global__ __launch_bounds__(TPB) void bspline_kernel(
    const float* __restrict__ ts,
    float4* __restrict__ out4,
    int n)
{
    __shared__ float sKN[20];
    __shared__ float sT[TPB * RSTR];      // 20 KB padded tile

    const int tid = threadIdx.x;

    if (tid < 20) sKN[tid] = KN[tid];

    // Zero the 16 data columns of this thread's row (pad cols never read).
    float4* rowz = (float4*)(sT + tid * RSTR);
    rowz[0] = make_float4(0.f, 0.f, 0.f, 0.f);
    rowz[1] = make_float4(0.f, 0.f, 0.f, 0.f);
    rowz[2] = make_float4(0.f, 0.f, 0.f, 0.f);
    rowz[3] = make_float4(0.f, 0.f, 0.f, 0.f);

    const long long limit4 = (long long)n * 4;
    int base = blockIdx.x * (TPB * TILES);

    // Prefetch first tile's t.
    int gi = base + tid;
    float t = ts[(gi < n) ? gi : (n - 1)];

    __syncthreads();   // knots + zero-fill visible

    #pragma unroll 1
    for (int k = 0; k < TILES; k++) {
        // ---- Phase 1: de Boor for the 4 nonzero basis functions ----
        int j = (int)(t * INV_H);
        j = max(0, min(12, j));
        j -= (j > 0)  && (t <  sKN[3 + j]);
        j += (j < 12) && (t >= sKN[4 + j]);

        const int span = j + 3;
        const float l1 = t - sKN[span];
        const float l2 = t - sKN[span - 1];
        const float l3 = t - sKN[span - 2];
        const float r1 = sKN[span + 1] - t;
        const float r2 = sKN[span + 2] - t;
        const float r3 = sKN[span + 3] - t;

        float N0 = 1.0f, N1, N2, N3, sv, tp;
        tp = __fdividef(N0, r1 + l1); N0 = r1 * tp; N1 = l1 * tp;
        tp = __fdividef(N0, r1 + l2); N0 = r1 * tp; sv = l2 * tp;
        tp = __fdividef(N1, r2 + l1); N1 = sv + r2 * tp; N2 = l1 * tp;
        tp = __fdividef(N0, r1 + l3); N0 = r1 * tp; sv = l3 * tp;
        tp = __fdividef(N1, r2 + l2); N1 = sv + r2 * tp; sv = l2 * tp;
        tp = __fdividef(N2, r3 + l1); N2 = sv + r3 * tp; N3 = l1 * tp;

        // Scatter the 4 nonzeros into this thread's (pre-zeroed) row.
        float* row = sT + tid * RSTR + j;
        row[0] = N0; row[1] = N1; row[2] = N2; row[3] = N3;

        // Prefetch next tile's t (overlaps with the barrier + copy-out).
        float tn = 0.0f;
        if (k + 1 < TILES) {
            int gn = base + (k + 1) * TPB + tid;
            tn = ts[(gn < n) ? gn : (n - 1)];
        }

        __syncthreads();   // tile fully scattered

        // ---- Phase 2: raw coalesced copy-out (no selects) ----
        // float4 slot f in [0,1024): element e = f>>2, chunk c = f&3.
        const long long obase = (long long)(base + k * TPB) * 4;
        float4* oblock = out4 + obase;

        #pragma unroll
        for (int i = 0; i < 4; i++) {
            const int f = tid + TPB * i;
            const float4 v = *(const float4*)(sT + (f >> 2) * RSTR + (f & 3) * 4);
            if (obase + f < limit4)
                oblock[f] = v;
        }

        __syncthreads();   // all readers done with the tile

        // Re-zero only this thread's 4 scattered cells for the next tile.
        row[0] = 0.f; row[1] = 0.f; row[2] = 0.f; row[3] = 0.f;

        t = tn;
    }
}

extern "C" void kernel_launch(void* const* d_in, const int* in_sizes, int n_in,
                              void* d_out, int out_size)
{
    const float* ts = (const float*)d_in[0];
    float4* out4 = (float4*)d_out;
    const int n = in_sizes[0];           // 32 * 131072 = 4194304 elements
    const int epb = TPB * TILES;
    const int blocks = (n + epb - 1) / epb;
    bspline_kernel<<<blocks, TPB>>>(ts, out4, n);
}